// round 6
// baseline (speedup 1.0000x reference)
#include <cuda_runtime.h>
#include <cstddef>

// Fixed shapes
#define T_STEPS 336
#define IN      16
#define H       64
#define NB      8
#define NT      512          // 16 warps -> 4 per SMSP
#define NCTAS   128

typedef unsigned long long u64;

// ---- shared memory layout (float offsets) ----
// Weights gate-interleaved, row stride 256: sh[off + k*256 + j*4 + gate] = W[gate*64+j][k]
#define OFF_W0X 0
#define OFF_W0H (OFF_W0X + IN*256)
#define OFF_W1X (OFF_W0H + H*256)
#define OFF_W1H (OFF_W1X + H*256)
#define OFF_X   (OFF_W1H + H*256)   // x duplicated: 16 rows x 16 floats (e0 e0 e1 e1 ...)
#define OFF_H0  (OFF_X + 256)       // h0 duplicated: 64 rows x 16 floats (single buffer)
#define OFF_H1  (OFF_H0 + 1024)     // h1 duplicated
#define OFF_P   (OFF_H1 + 1024)     // partial-exchange buffer: 1024 u64 = 2048 floats
                                    // (also reused to stage biases during init)
#define SMEM_FLOATS (OFF_P + 2048)  // 57,600 floats
#define SMEM_BYTES  (SMEM_FLOATS * 4) // 230,400 B  (< 232,448 cap)

// ---- packed f32x2 helpers ----
__device__ __forceinline__ u64 fma2(u64 a, u64 b, u64 c) {
    u64 d;
    asm("fma.rn.f32x2 %0, %1, %2, %3;" : "=l"(d) : "l"(a), "l"(b), "l"(c));
    return d;
}
__device__ __forceinline__ u64 add2(u64 a, u64 b) {
    u64 d;
    asm("add.rn.f32x2 %0, %1, %2;" : "=l"(d) : "l"(a), "l"(b));
    return d;
}
__device__ __forceinline__ ulonglong2 lds2(const float* p) {
    return *reinterpret_cast<const ulonglong2*>(p);
}
__device__ __forceinline__ float lo32(u64 v) {
    return __uint_as_float((unsigned)(v & 0xffffffffu));
}
__device__ __forceinline__ float hi32(u64 v) {
    return __uint_as_float((unsigned)(v >> 32));
}

__device__ __forceinline__ float sigf(float x) {
    return 1.0f / (1.0f + __expf(-x));
}
__device__ __forceinline__ float tanh_ex(float x) {
    return 1.0f - 2.0f / (__expf(2.0f * x) + 1.0f);
}

// GEMM over NCH chunks of 4 k. wbase: gate-interleaved weight rows (stride 256 floats,
// offset j*4 baked in). ibase: duplicated input rows (stride 16 floats, offset e0*2 baked in).
template<int NCH>
__device__ __forceinline__ void gemm(u64 aif[4], u64 ago[4],
                                     const float* __restrict__ wbase,
                                     const float* __restrict__ ibase)
{
#pragma unroll
    for (int c = 0; c < NCH; ++c) {
#pragma unroll
        for (int ki = 0; ki < 4; ++ki) {
            const int k = c * 4 + ki;
            const ulonglong2 w  = lds2(wbase + k * 256);     // (wi,wf),(wg,wo)
            const ulonglong2 ha = lds2(ibase + k * 16);      // (he0,he0),(he1,he1)
            const ulonglong2 hb = lds2(ibase + k * 16 + 4);  // (he2,he2),(he3,he3)
            aif[0] = fma2(w.x, ha.x, aif[0]); ago[0] = fma2(w.y, ha.x, ago[0]);
            aif[1] = fma2(w.x, ha.y, aif[1]); ago[1] = fma2(w.y, ha.y, ago[1]);
            aif[2] = fma2(w.x, hb.x, aif[2]); ago[2] = fma2(w.y, hb.x, ago[2]);
            aif[3] = fma2(w.x, hb.y, aif[3]); ago[3] = fma2(w.y, hb.y, ago[3]);
        }
    }
}

// intra-warp split-K combine: kp halves (xor 16) summed as packed f32 pairs
__device__ __forceinline__ void comb8(u64 aif[4], u64 ago[4]) {
#pragma unroll
    for (int i = 0; i < 4; ++i) {
        aif[i] = add2(aif[i], __shfl_xor_sync(0xffffffffu, aif[i], 16));
        ago[i] = add2(ago[i], __shfl_xor_sync(0xffffffffu, ago[i], 16));
    }
}

// activation for one element; updates c, returns h
__device__ __forceinline__ float actv(u64 vif, u64 vgo, float& c) {
    const float i = sigf(lo32(vif));
    const float f = sigf(hi32(vif));
    const float g = tanh_ex(lo32(vgo));
    const float o = sigf(hi32(vgo));
    c = fmaf(f, c, i * g);
    return o * tanh_ex(c);
}

__global__ void __launch_bounds__(NT, 1)
lstm2_kernel(const float* __restrict__ x,
             const float* __restrict__ Wih0, const float* __restrict__ Whh0,
             const float* __restrict__ bih0, const float* __restrict__ bhh0,
             const float* __restrict__ Wih1, const float* __restrict__ Whh1,
             const float* __restrict__ bih1, const float* __restrict__ bhh1,
             const float* __restrict__ Wfc,  const float* __restrict__ bfc,
             float* __restrict__ out)
{
    extern __shared__ float sh[];
    const int tid = threadIdx.x;

    // ---- stage weights gate-interleaved, stride 256 ----
    for (int idx = tid; idx < 256 * IN; idx += NT) {
        const int gr = idx >> 4, k = idx & 15;
        sh[OFF_W0X + k * 256 + (gr & 63) * 4 + (gr >> 6)] = Wih0[idx];
    }
    for (int idx = tid; idx < 256 * H; idx += NT) {
        const int gr = idx >> 6, k = idx & 63;
        sh[OFF_W0H + k * 256 + (gr & 63) * 4 + (gr >> 6)] = Whh0[idx];
    }
    for (int idx = tid; idx < 256 * H; idx += NT) {
        const int gr = idx >> 6, k = idx & 63;
        sh[OFF_W1X + k * 256 + (gr & 63) * 4 + (gr >> 6)] = Wih1[idx];
    }
    for (int idx = tid; idx < 256 * H; idx += NT) {
        const int gr = idx >> 6, k = idx & 63;
        sh[OFF_W1H + k * 256 + (gr & 63) * 4 + (gr >> 6)] = Whh1[idx];
    }
    // stage combined biases (gate-interleaved) into the P region temporarily
    {
        if (tid < 256) {
            const int gate = tid >> 6, jj = tid & 63;
            sh[OFF_P + jj * 4 + gate] = bih0[tid] + bhh0[tid];
        } else {
            const int i2 = tid - 256, gate = i2 >> 6, jj = i2 & 63;
            sh[OFF_P + 256 + jj * 4 + gate] = bih1[i2] + bhh1[i2];
        }
    }
    // zero duplicated h buffers (h0 then h1, contiguous 2048 floats)
    for (int idx = tid; idx < 2048; idx += NT) sh[OFF_H0 + idx] = 0.0f;

    // ---- thread mapping ----
    const int wid  = tid >> 5, lane = tid & 31;
    const int eg   = wid >> 3;          // element group: 0 -> elems 0-3, 1 -> 4-7
    const int kq2  = (wid >> 2) & 1;    // k-half bit (warp level)
    const int jq   = wid & 3;           // j quarter
    const int hl   = lane & 15;
    const int kp   = lane >> 4;         // k-sub bit (lane level)
    const int j    = jq * 16 + hl;
    const int kk   = kq2 * 2 + kp;      // k quarter 0..3
    const int e0   = eg * 4;

    // producers: warps 4-7 (kq2=1, eg=0) handle x staging
    const bool producer = (wid >= 4 && wid < 8);
    const int pid = tid - 128;                       // 0..127 for producers
    const int xe = pid >> 4, xk = pid & 15;
    const float* xptr = x + ((size_t)(blockIdx.x * NB + xe) * T_STEPS) * IN + xk;

    float xreg = 0.0f;
    if (producer) {
        // stage x(0) duplicated, prefetch x(1)
        const float x0 = xptr[0];
        *reinterpret_cast<float2*>(&sh[OFF_X + xk * 16 + xe * 2]) = make_float2(x0, x0);
        xreg = xptr[IN];                 // x(1)
    }
    __syncthreads();

    // biases into registers (from P staging), then release P
    const ulonglong2 b0 = lds2(&sh[OFF_P + j * 4]);
    const ulonglong2 b1 = lds2(&sh[OFF_P + 256 + j * 4]);
    __syncthreads();   // P reads done before first partial store

    u64* const P = reinterpret_cast<u64*>(&sh[OFF_P]);
    const int ps = (eg * 4 + jq) * 16 + hl;          // partial slot 0..127

    float c0[4] = {0.f, 0.f, 0.f, 0.f};
    float c1[4] = {0.f, 0.f, 0.f, 0.f};

    for (int t = 0; t < T_STEPS; ++t) {
        __syncthreads();                               // BAR A: h1(t-1)/P(t-1) settled

        // ================= Layer 0 =================
        u64 aif[4] = {0, 0, 0, 0}, ago[4] = {0, 0, 0, 0};
        gemm<1>(aif, ago, &sh[OFF_W0X + (kk * 4)  * 256 + j * 4],
                          &sh[OFF_X   + (kk * 4)  * 16  + e0 * 2]);
        gemm<4>(aif, ago, &sh[OFF_W0H + (kk * 16) * 256 + j * 4],
                          &sh[OFF_H0  + (kk * 16) * 16  + e0 * 2]);
        comb8(aif, ago);
        if (kq2) {
            if (kp == 0) {
#pragma unroll
                for (int i = 0; i < 4; ++i) {
                    P[(2 * i)     * 128 + ps] = aif[i];
                    P[(2 * i + 1) * 128 + ps] = ago[i];
                }
            }
        }
        __syncthreads();                               // BAR B: partials visible; all h0/x reads done
        if (!kq2) {
            if (kp == 0) {
#pragma unroll
                for (int i = 0; i < 4; ++i) {
                    aif[i] = add2(add2(aif[i], P[(2 * i) * 128 + ps]), b0.x);
                    ago[i] = add2(add2(ago[i], P[(2 * i + 1) * 128 + ps]), b0.y);
                }
#pragma unroll
                for (int e = 0; e < 4; ++e) {
                    const float h = actv(aif[e], ago[e], c0[e]);
                    *reinterpret_cast<float2*>(&sh[OFF_H0 + j * 16 + (e0 + e) * 2]) =
                        make_float2(h, h);
                }
            }
        } else if (producer) {
            if (t + 1 < T_STEPS)
                *reinterpret_cast<float2*>(&sh[OFF_X + xk * 16 + xe * 2]) =
                    make_float2(xreg, xreg);
            if (t + 2 < T_STEPS) xreg = xptr[(size_t)(t + 2) * IN];
        }
        __syncthreads();                               // BAR D: h0(t)/x(t+1) visible

        // ================= Layer 1 =================
        u64 bifa[4] = {0, 0, 0, 0}, bgoa[4] = {0, 0, 0, 0};
        gemm<4>(bifa, bgoa, &sh[OFF_W1X + (kk * 16) * 256 + j * 4],
                            &sh[OFF_H0  + (kk * 16) * 16  + e0 * 2]);
        gemm<4>(bifa, bgoa, &sh[OFF_W1H + (kk * 16) * 256 + j * 4],
                            &sh[OFF_H1  + (kk * 16) * 16  + e0 * 2]);
        comb8(bifa, bgoa);
        if (kq2) {
            if (kp == 0) {
#pragma unroll
                for (int i = 0; i < 4; ++i) {
                    P[(2 * i)     * 128 + ps] = bifa[i];
                    P[(2 * i + 1) * 128 + ps] = bgoa[i];
                }
            }
        }
        __syncthreads();                               // BAR E: partials visible; all h1 reads done
        if (!kq2 && kp == 0) {
#pragma unroll
            for (int i = 0; i < 4; ++i) {
                bifa[i] = add2(add2(bifa[i], P[(2 * i) * 128 + ps]), b1.x);
                bgoa[i] = add2(add2(bgoa[i], P[(2 * i + 1) * 128 + ps]), b1.y);
            }
#pragma unroll
            for (int e = 0; e < 4; ++e) {
                const float h = actv(bifa[e], bgoa[e], c1[e]);
                *reinterpret_cast<float2*>(&sh[OFF_H1 + j * 16 + (e0 + e) * 2]) =
                    make_float2(h, h);
            }
        }
    }

    __syncthreads();

    // ---- FC head: out[b] = dot(Wfc, h1_last[b]) + bfc ----
    if (tid < NB) {
        float s = 0.0f;
#pragma unroll 8
        for (int k = 0; k < H; ++k) s += Wfc[k] * sh[OFF_H1 + k * 16 + tid * 2];
        out[blockIdx.x * NB + tid] = s + bfc[0];
    }
}

extern "C" void kernel_launch(void* const* d_in, const int* in_sizes, int n_in,
                              void* d_out, int out_size)
{
    const float* x    = (const float*)d_in[0];
    const float* Wih0 = (const float*)d_in[1];
    const float* Whh0 = (const float*)d_in[2];
    const float* bih0 = (const float*)d_in[3];
    const float* bhh0 = (const float*)d_in[4];
    const float* Wih1 = (const float*)d_in[5];
    const float* Whh1 = (const float*)d_in[6];
    const float* bih1 = (const float*)d_in[7];
    const float* bhh1 = (const float*)d_in[8];
    const float* Wfc  = (const float*)d_in[9];
    const float* bfc  = (const float*)d_in[10];
    float* out = (float*)d_out;

    cudaFuncSetAttribute(lstm2_kernel,
                         cudaFuncAttributeMaxDynamicSharedMemorySize, SMEM_BYTES);
    lstm2_kernel<<<NCTAS, NT, SMEM_BYTES>>>(
        x, Wih0, Whh0, bih0, bhh0, Wih1, Whh1, bih1, bhh1, Wfc, bfc, out);
}

// round 7
// speedup vs baseline: 1.8470x; 1.8470x over previous
#include <cuda_runtime.h>
#include <cstddef>

// Fixed shapes
#define T_STEPS 336
#define NT      256          // 8 warps, 2 per SMSP
#define NCTAS   128          // 8 batch elems per CTA

typedef unsigned long long u64;

// ---- shared memory layout (float offsets) ----
// Weights: per k-pair row (stride WS=520 floats):
//   floats [0..255]  : plane01 -> j*4 + {Wi_k, Wi_k1, Wf_k, Wf_k1}
//   floats [256..511]: plane23 -> j*4 + {Wg_k, Wg_k1, Wo_k, Wo_k1}
// Rows within a segment interleaved by split-K half: row = local_pair*2 + kpar.
#define WS      520
#define OFF_W0X 0            // K=16  -> 8 rows
#define OFF_W0H 4160         // K=64  -> 32 rows
#define OFF_W1X 20800        // K=64  -> 32 rows
#define OFF_W1H 37440        // K=64  -> 32 rows
#define OFF_B   54080        // 512: combined biases, [layer*256 + gate*64 + j]
#define OFF_X   54592        // 2 bufs x (8 elems x 20)
#define OFF_H0  54912        // 2 bufs x (8 elems x 68), k-swizzled pos(k)=k+(k>=32)*4
#define OFF_H1  56000        // 2 bufs x 544
#define SMEM_FLOATS 57088
#define SMEM_BYTES (SMEM_FLOATS * 4)   // 228,352 B < 232,448 cap

// ---- packed helpers ----
__device__ __forceinline__ u64 fma2(u64 a, u64 b, u64 c) {
    u64 d;
    asm("fma.rn.f32x2 %0, %1, %2, %3;" : "=l"(d) : "l"(a), "l"(b), "l"(c));
    return d;
}
__device__ __forceinline__ ulonglong2 lds2(const float* p) {
    return *reinterpret_cast<const ulonglong2*>(p);
}
__device__ __forceinline__ float foldadd(u64 v) {
    float lo, hi;
    asm("mov.b64 {%0,%1}, %2;" : "=f"(lo), "=f"(hi) : "l"(v));
    return lo + hi;
}
__device__ __forceinline__ float sigf(float x) {
    return __fdividef(1.0f, 1.0f + __expf(-x));
}
__device__ __forceinline__ float tanhe(float x) {
    return 1.0f - __fdividef(2.0f, __expf(2.0f * x) + 1.0f);
}

// GEMM over NCH chunks of 4 k (= 2 k-pairs). acc[gate*4+e], gates i,f,g,o.
// wbase: segment base + kpar*WS + j*4 baked in. hbase: buf + e0*HS + kpar-k-offset baked in.
template<int NCH, int HS>
__device__ __forceinline__ void gemm2(u64* __restrict__ acc,
                                      const float* __restrict__ wbase,
                                      const float* __restrict__ hbase)
{
#pragma unroll
    for (int c = 0; c < NCH; ++c) {
        ulonglong2 hv0 = lds2(hbase + 0 * HS + c * 4);
        ulonglong2 hv1 = lds2(hbase + 1 * HS + c * 4);
        ulonglong2 hv2 = lds2(hbase + 2 * HS + c * 4);
        ulonglong2 hv3 = lds2(hbase + 3 * HS + c * 4);
#pragma unroll
        for (int ki2 = 0; ki2 < 2; ++ki2) {
            const float* wr = wbase + (size_t)(4 * c + 2 * ki2) * WS;
            const ulonglong2 wif = lds2(wr);
            const ulonglong2 wgo = lds2(wr + 256);
            const u64 h0 = ki2 ? hv0.y : hv0.x;
            const u64 h1 = ki2 ? hv1.y : hv1.x;
            const u64 h2 = ki2 ? hv2.y : hv2.x;
            const u64 h3 = ki2 ? hv3.y : hv3.x;
            acc[0]  = fma2(wif.x, h0, acc[0]);
            acc[1]  = fma2(wif.x, h1, acc[1]);
            acc[2]  = fma2(wif.x, h2, acc[2]);
            acc[3]  = fma2(wif.x, h3, acc[3]);
            acc[4]  = fma2(wif.y, h0, acc[4]);
            acc[5]  = fma2(wif.y, h1, acc[5]);
            acc[6]  = fma2(wif.y, h2, acc[6]);
            acc[7]  = fma2(wif.y, h3, acc[7]);
            acc[8]  = fma2(wgo.x, h0, acc[8]);
            acc[9]  = fma2(wgo.x, h1, acc[9]);
            acc[10] = fma2(wgo.x, h2, acc[10]);
            acc[11] = fma2(wgo.x, h3, acc[11]);
            acc[12] = fma2(wgo.y, h0, acc[12]);
            acc[13] = fma2(wgo.y, h1, acc[13]);
            acc[14] = fma2(wgo.y, h2, acc[14]);
            acc[15] = fma2(wgo.y, h3, acc[15]);
        }
    }
}

__global__ void __launch_bounds__(NT, 1)
lstm2_kernel(const float* __restrict__ x,
             const float* __restrict__ Wih0, const float* __restrict__ Whh0,
             const float* __restrict__ bih0, const float* __restrict__ bhh0,
             const float* __restrict__ Wih1, const float* __restrict__ Whh1,
             const float* __restrict__ bih1, const float* __restrict__ bhh1,
             const float* __restrict__ Wfc,  const float* __restrict__ bfc,
             float* __restrict__ out)
{
    extern __shared__ float sh[];
    const int tid = threadIdx.x;

    // ---- stage weights into k-pair-packed layout ----
    // K=16 segment (W_ih0)
    for (int idx = tid; idx < 256 * 16; idx += NT) {
        const int gr = idx >> 4, k = idx & 15;
        const int g = gr >> 6, j = gr & 63;
        const int p2 = k >> 1;
        const int kh = (p2 >= 4) ? 1 : 0;
        const int row = (p2 - kh * 4) * 2 + kh;
        sh[OFF_W0X + row * WS + (g >> 1) * 256 + j * 4 + (g & 1) * 2 + (k & 1)] = Wih0[idx];
    }
    // K=64 segments
    for (int idx = tid; idx < 256 * 64; idx += NT) {
        const int gr = idx >> 6, k = idx & 63;
        const int g = gr >> 6, j = gr & 63;
        const int p2 = k >> 1;
        const int kh = (p2 >= 16) ? 1 : 0;
        const int row = (p2 - kh * 16) * 2 + kh;
        const int o = row * WS + (g >> 1) * 256 + j * 4 + (g & 1) * 2 + (k & 1);
        sh[OFF_W0H + o] = Whh0[idx];
        sh[OFF_W1X + o] = Wih1[idx];
        sh[OFF_W1H + o] = Whh1[idx];
    }
    // combined biases
    if (tid < 256) {
        sh[OFF_B + tid]       = bih0[tid] + bhh0[tid];
        sh[OFF_B + 256 + tid] = bih1[tid] + bhh1[tid];
    }
    // zero h buffers (both layers, both buffers)
    for (int idx = tid; idx < 2176; idx += NT) sh[OFF_H0 + idx] = 0.0f;

    // ---- thread mapping: warp = (eg, jq); lane = (kp, hl) ----
    const int wid = tid >> 5, lane = tid & 31;
    const int eg  = wid >> 2;           // elems [eg*4, eg*4+4)
    const int jq  = wid & 3;
    const int hl  = lane & 15;
    const int kp  = lane >> 4;          // split-K half
    const int j   = jq * 16 + hl;
    const int e0  = eg * 4;

    // x staging owned by kp==1 lanes: pid 0..127 -> (elem, k)
    const int pid = wid * 16 + hl;
    const int xe = pid >> 4, xk = pid & 15;
    const float* xptr = x + ((size_t)(blockIdx.x * 8 + xe) * T_STEPS) * 16 + xk;
    float xreg = 0.0f;
    if (kp == 1) {
        sh[OFF_X + xe * 20 + xk] = xptr[0];   // x(0) -> buf 0
        xreg = xptr[16];                      // prefetch x(1)
    }
    __syncthreads();

    // biases into registers
    const float b0i = sh[OFF_B +   0 + j], b0f = sh[OFF_B +  64 + j];
    const float b0g = sh[OFF_B + 128 + j], b0o = sh[OFF_B + 192 + j];
    const float b1i = sh[OFF_B + 256 + j], b1f = sh[OFF_B + 320 + j];
    const float b1g = sh[OFF_B + 384 + j], b1o = sh[OFF_B + 448 + j];

    // baked base pointers
    const float* w0x = &sh[OFF_W0X + kp * WS + j * 4];
    const float* w0h = &sh[OFF_W0H + kp * WS + j * 4];
    const float* w1x = &sh[OFF_W1X + kp * WS + j * 4];
    const float* w1h = &sh[OFF_W1H + kp * WS + j * 4];
    const int hko = kp * 36;            // swizzled k-offset for kpar half (pos(32)=36)
    const int pj  = j + ((j >> 5) << 2); // pos(j) for h stores
    float c0[4] = {0.f, 0.f, 0.f, 0.f};
    float c1[4] = {0.f, 0.f, 0.f, 0.f};

    int p = 0;
    for (int t = 0; t < T_STEPS; ++t) {
        __syncthreads();   // BAR A: x(t), h1(t-1), h0(t-1) visible

        // ================= Layer 0 =================
        u64 acc[16];
#pragma unroll
        for (int i = 0; i < 16; ++i) acc[i] = 0ull;
        gemm2<2, 20>(acc, w0x, &sh[OFF_X + p * 160 + e0 * 20 + kp * 8]);
        gemm2<8, 68>(acc, w0h, &sh[OFF_H0 + p * 544 + e0 * 68 + hko]);

        float s[16];
#pragma unroll
        for (int i = 0; i < 16; ++i) s[i] = foldadd(acc[i]);
#pragma unroll
        for (int i = 0; i < 16; ++i) s[i] += __shfl_xor_sync(0xffffffffu, s[i], 16);

        if (kp == 0) {
            float* hw = &sh[OFF_H0 + (1 - p) * 544 + e0 * 68 + pj];
#pragma unroll
            for (int e = 0; e < 4; ++e) {
                const float gi = sigf(s[e] + b0i);
                const float gf = sigf(s[4 + e] + b0f);
                const float gg = tanhe(s[8 + e] + b0g);
                const float go = sigf(s[12 + e] + b0o);
                c0[e] = fmaf(gf, c0[e], gi * gg);
                hw[e * 68] = go * tanhe(c0[e]);
            }
        } else {
            if (t + 1 < T_STEPS) sh[OFF_X + (1 - p) * 160 + xe * 20 + xk] = xreg;
            if (t + 2 < T_STEPS) xreg = xptr[(size_t)(t + 2) * 16];
        }
        __syncthreads();   // BAR B: h0(t), x(t+1) visible

        // ================= Layer 1 =================
#pragma unroll
        for (int i = 0; i < 16; ++i) acc[i] = 0ull;
        gemm2<8, 68>(acc, w1x, &sh[OFF_H0 + (1 - p) * 544 + e0 * 68 + hko]);
        gemm2<8, 68>(acc, w1h, &sh[OFF_H1 + p * 544 + e0 * 68 + hko]);

#pragma unroll
        for (int i = 0; i < 16; ++i) s[i] = foldadd(acc[i]);
#pragma unroll
        for (int i = 0; i < 16; ++i) s[i] += __shfl_xor_sync(0xffffffffu, s[i], 16);

        if (kp == 0) {
            float* hw = &sh[OFF_H1 + (1 - p) * 544 + e0 * 68 + pj];
#pragma unroll
            for (int e = 0; e < 4; ++e) {
                const float gi = sigf(s[e] + b1i);
                const float gf = sigf(s[4 + e] + b1f);
                const float gg = tanhe(s[8 + e] + b1g);
                const float go = sigf(s[12 + e] + b1o);
                c1[e] = fmaf(gf, c1[e], gi * gg);
                hw[e * 68] = go * tanhe(c1[e]);
            }
        }
        p ^= 1;
    }

    __syncthreads();

    // ---- FC head: out[b] = dot(Wfc, h1_last[b]) + bfc ----
    // after the loop, last h1 write went to buffer p
    if (tid < 8) {
        const float* hv = &sh[OFF_H1 + p * 544 + tid * 68];
        float sum = 0.0f;
#pragma unroll 8
        for (int k = 0; k < 64; ++k) sum += Wfc[k] * hv[k + ((k >> 5) << 2)];
        out[blockIdx.x * 8 + tid] = sum + bfc[0];
    }
}

extern "C" void kernel_launch(void* const* d_in, const int* in_sizes, int n_in,
                              void* d_out, int out_size)
{
    const float* x    = (const float*)d_in[0];
    const float* Wih0 = (const float*)d_in[1];
    const float* Whh0 = (const float*)d_in[2];
    const float* bih0 = (const float*)d_in[3];
    const float* bhh0 = (const float*)d_in[4];
    const float* Wih1 = (const float*)d_in[5];
    const float* Whh1 = (const float*)d_in[6];
    const float* bih1 = (const float*)d_in[7];
    const float* bhh1 = (const float*)d_in[8];
    const float* Wfc  = (const float*)d_in[9];
    const float* bfc  = (const float*)d_in[10];
    float* out = (float*)d_out;

    cudaFuncSetAttribute(lstm2_kernel,
                         cudaFuncAttributeMaxDynamicSharedMemorySize, SMEM_BYTES);
    lstm2_kernel<<<NCTAS, NT, SMEM_BYTES>>>(
        x, Wih0, Whh0, bih0, bhh0, Wih1, Whh1, bih1, bhh1, Wfc, bfc, out);
}